// round 7
// baseline (speedup 1.0000x reference)
#include <cuda_runtime.h>
#include <cuda_fp16.h>
#include <cstdint>

#define TT 140
#define HH 128
#define BT 32
#define NCTA 128
#define NTHR 512

#define WSTRIDE 136                    // halfs per weight row (272 B, conflict-free LDSM)
#define WROWS   640                    // 512 gate rows + 128 W1 rows
#define WBYTES  (WROWS*WSTRIDE*2)      // 174080
#define HSTRIDE 40                     // halfs per h row (80 B, conflict-free)
#define HBYTES  (HH*HSTRIDE*2)         // 10240
#define OFF_W   0
#define OFF_H   WBYTES                 // two h buffers
#define OFF_X   (OFF_H + 2*HBYTES)     // x_sh [t][b] f32; reused as r1_sh in tail
#define SMEM_BYTES (OFF_X + TT*BT*4)   // 212480

// f16 weights, padded layout: rows 0..511 = W_hh (gate-major), rows 512..639 = W1
__device__ __align__(16) unsigned short g_W16[WROWS*WSTRIDE];

// ---------------- helpers ----------------
__device__ __forceinline__ uint32_t smem_u32(const void* p){
    uint32_t a;
    asm("{ .reg .u64 t; cvta.to.shared.u64 t, %1; cvt.u32.u64 %0, t; }"
        : "=r"(a) : "l"(p));
    return a;
}
__device__ __forceinline__ void cp_async16(void* s, const void* g){
    unsigned a = smem_u32(s);
    asm volatile("cp.async.cg.shared.global [%0],[%1],16;" :: "r"(a), "l"(g));
}
__device__ __forceinline__ void ldsm4(uint32_t* r, uint32_t addr){
    asm volatile("ldmatrix.sync.aligned.m8n8.x4.shared.b16 {%0,%1,%2,%3},[%4];"
        : "=r"(r[0]),"=r"(r[1]),"=r"(r[2]),"=r"(r[3]) : "r"(addr));
}
__device__ __forceinline__ void ldsm4t(uint32_t* r, uint32_t addr){
    asm volatile("ldmatrix.sync.aligned.m8n8.x4.trans.shared.b16 {%0,%1,%2,%3},[%4];"
        : "=r"(r[0]),"=r"(r[1]),"=r"(r[2]),"=r"(r[3]) : "r"(addr));
}
__device__ __forceinline__ void mma16816(float* d, const uint32_t* a,
                                         uint32_t b0, uint32_t b1){
    asm volatile("mma.sync.aligned.m16n8k16.row.col.f32.f16.f16.f32 "
        "{%0,%1,%2,%3},{%4,%5,%6,%7},{%8,%9},{%0,%1,%2,%3};"
        : "+f"(d[0]),"+f"(d[1]),"+f"(d[2]),"+f"(d[3])
        : "r"(a[0]),"r"(a[1]),"r"(a[2]),"r"(a[3]),"r"(b0),"r"(b1));
}
__device__ __forceinline__ float mufu_tanh(float x){
    float r;
    asm("tanh.approx.f32 %0,%1;" : "=f"(r) : "f"(x));
    return r;
}
__device__ __forceinline__ float fast_sigmoid(float x){
    return fmaf(0.5f, mufu_tanh(0.5f * x), 0.5f);
}

// ---------------- prep: convert weights to f16 padded layout ----------------
__global__ void prep_kernel(const float* __restrict__ Whh,
                            const float* __restrict__ W1){
    int i = blockIdx.x * blockDim.x + threadIdx.x;
    int stride = gridDim.x * blockDim.x;
    for (int idx = i; idx < WROWS*HH; idx += stride){
        int row = idx >> 7, k = idx & 127;
        float v = (row < 512) ? Whh[row*HH + k] : W1[(row - 512)*HH + k];
        __half hv = __float2half_rn(v);
        g_W16[row*WSTRIDE + k] = *(unsigned short*)&hv;
    }
}

// ---------------- main persistent LSTM kernel ----------------
__global__ __launch_bounds__(NTHR, 1)
void lstm_kernel(const float* __restrict__ x,
                 const float* __restrict__ Wih,
                 const float* __restrict__ bih,
                 const float* __restrict__ bhh,
                 const float* __restrict__ b1,
                 const float* __restrict__ W2,
                 const float* __restrict__ b2,
                 float* __restrict__ out){
    extern __shared__ char sm[];
    const uint32_t smb = smem_u32(sm);
    const int tid  = threadIdx.x;
    const int lane = tid & 31;
    const int w    = tid >> 5;          // warp 0..15
    const int wu   = w & 7;             // unit group: units 16wu..16wu+15
    const int bh   = w >> 3;            // batch half: 0 -> b0..15, 1 -> b16..31
    const int b0   = blockIdx.x * BT;
    float* x_sh = (float*)(sm + OFF_X);

    // ---- stage W (f16) via cp.async; x; zero h buffer 0 ----
    for (int i = tid*16; i < WBYTES; i += NTHR*16)
        cp_async16(sm + OFF_W + i, (const char*)g_W16 + i);
    asm volatile("cp.async.commit_group;" ::: "memory");
    for (int idx = tid; idx < TT*BT; idx += NTHR){
        int t = idx >> 5, b = idx & 31;
        x_sh[t*32 + b] = x[(size_t)(b0 + b)*TT + t];
    }
    for (int i = tid; i < HBYTES/4; i += NTHR)
        ((float*)(sm + OFF_H))[i] = 0.0f;
    asm volatile("cp.async.wait_group 0;" ::: "memory");
    __syncthreads();

    // ---- per-thread constants ----
    const int u0 = 16*wu + (lane >> 2);
    const int u1 = u0 + 8;
    float wi[4][2], bs[4][2];
    #pragma unroll
    for (int g = 0; g < 4; g++){
        wi[g][0] = Wih[g*HH + u0];
        wi[g][1] = Wih[g*HH + u1];
        bs[g][0] = bih[g*HH + u0] + bhh[g*HH + u0];
        bs[g][1] = bih[g*HH + u1] + bhh[g*HH + u1];
    }
    float c0[4], c1[4];
    #pragma unroll
    for (int i = 0; i < 4; i++){ c0[i] = 0.0f; c1[i] = 0.0f; }

    // ldmatrix address bases
    uint32_t Abase[4];
    #pragma unroll
    for (int mt = 0; mt < 4; mt++)
        Abase[mt] = smb + OFF_W +
            (uint32_t)(((mt*128 + 16*wu + (lane & 15))*WSTRIDE + (lane >> 4)*8) * 2);
    const uint32_t AbaseT = smb + OFF_W +
            (uint32_t)(((512 + 16*wu + (lane & 15))*WSTRIDE + (lane >> 4)*8) * 2);
    const uint32_t Brow = (uint32_t)((lane & 7) + ((lane >> 3) & 1)*8);
    // h fragment base for this warp's 16-batch half
    const uint32_t Bb = smb + OFF_H + Brow*(HSTRIDE*2)
                      + (uint32_t)((lane >> 4)*8)*2 + (uint32_t)bh*32;
    const int bq   = 2*(lane & 3);          // batch pair within n8 tile
    const int bco  = bh*16 + bq;            // batch column offset base

    uint32_t bsel = 0;
    for (int t = 0; t < TT; t++){
        // init accumulators with bias + x_t * w_in
        float acc[4][2][4];
        float xv[2][2];
        #pragma unroll
        for (int nt = 0; nt < 2; nt++){
            xv[nt][0] = x_sh[t*32 + bco + 8*nt];
            xv[nt][1] = x_sh[t*32 + bco + 8*nt + 1];
        }
        #pragma unroll
        for (int mt = 0; mt < 4; mt++)
            #pragma unroll
            for (int nt = 0; nt < 2; nt++){
                acc[mt][nt][0] = fmaf(xv[nt][0], wi[mt][0], bs[mt][0]);
                acc[mt][nt][1] = fmaf(xv[nt][1], wi[mt][0], bs[mt][0]);
                acc[mt][nt][2] = fmaf(xv[nt][0], wi[mt][1], bs[mt][1]);
                acc[mt][nt][3] = fmaf(xv[nt][1], wi[mt][1], bs[mt][1]);
            }

        // gates += W @ h   (K = 128, 8 k-chunks)
        const uint32_t Bc = Bb + bsel;
        #pragma unroll
        for (int kc = 0; kc < 8; kc++){
            uint32_t bfr[4];
            ldsm4t(bfr, Bc + kc*(16*HSTRIDE*2));
            #pragma unroll
            for (int mt = 0; mt < 4; mt++){
                uint32_t a[4];
                ldsm4(a, Abase[mt] + kc*32);
                mma16816(acc[mt][0], a, bfr[0], bfr[1]);
                mma16816(acc[mt][1], a, bfr[2], bfr[3]);
            }
        }

        // elementwise LSTM update (all 4 gates thread-local), write h to other buffer
        const uint32_t wsel = bsel ^ HBYTES;
        #pragma unroll
        for (int nt = 0; nt < 2; nt++){
            float hv0[2], hv1[2];
            #pragma unroll
            for (int j = 0; j < 2; j++){
                int ci = nt*2 + j;
                {   // unit u0
                    float iv = fast_sigmoid(acc[0][nt][j]);
                    float fv = fast_sigmoid(acc[1][nt][j]);
                    float gv = mufu_tanh   (acc[2][nt][j]);
                    float ov = fast_sigmoid(acc[3][nt][j]);
                    float cv = fv * c0[ci] + iv * gv;
                    c0[ci] = cv;
                    hv0[j] = ov * mufu_tanh(cv);
                }
                {   // unit u1
                    float iv = fast_sigmoid(acc[0][nt][2+j]);
                    float fv = fast_sigmoid(acc[1][nt][2+j]);
                    float gv = mufu_tanh   (acc[2][nt][2+j]);
                    float ov = fast_sigmoid(acc[3][nt][2+j]);
                    float cv = fv * c1[ci] + iv * gv;
                    c1[ci] = cv;
                    hv1[j] = ov * mufu_tanh(cv);
                }
            }
            int boff = (bco + 8*nt)*2;
            *(half2*)(sm + OFF_H + wsel + u0*(HSTRIDE*2) + boff) =
                __floats2half2_rn(hv0[0], hv0[1]);
            *(half2*)(sm + OFF_H + wsel + u1*(HSTRIDE*2) + boff) =
                __floats2half2_rn(hv1[0], hv1[1]);
        }
        __syncthreads();
        bsel = wsel;
    }
    // final h is in buffer with byte-offset bsel (= 0 for TT even)

    // ---- MLP head: r1 = relu(W1 @ h + b1) via the same MMA path ----
    float racc[2][4];
    {
        float bv0 = b1[u0], bv1 = b1[u1];
        #pragma unroll
        for (int nt = 0; nt < 2; nt++){
            racc[nt][0] = bv0; racc[nt][1] = bv0;
            racc[nt][2] = bv1; racc[nt][3] = bv1;
        }
    }
    {
        const uint32_t Bc = Bb + bsel;
        #pragma unroll
        for (int kc = 0; kc < 8; kc++){
            uint32_t bfr[4];
            ldsm4t(bfr, Bc + kc*(16*HSTRIDE*2));
            uint32_t a[4];
            ldsm4(a, AbaseT + kc*32);
            mma16816(racc[0], a, bfr[0], bfr[1]);
            mma16816(racc[1], a, bfr[2], bfr[3]);
        }
    }
    __syncthreads();            // x_sh reads done; reuse as r1_sh
    float* r1_sh = (float*)(sm + OFF_X);   // [b][n] f32
    #pragma unroll
    for (int nt = 0; nt < 2; nt++)
        #pragma unroll
        for (int j = 0; j < 2; j++){
            int b = bco + 8*nt + j;
            r1_sh[b*HH + u0] = fmaxf(racc[nt][j],     0.0f);
            r1_sh[b*HH + u1] = fmaxf(racc[nt][2 + j], 0.0f);
        }
    __syncthreads();
    // stage W2 (5x128 f32) into h region (done with h)
    float* w2sh = (float*)(sm + OFF_H);
    for (int idx = tid; idx < 5*HH; idx += NTHR) w2sh[idx] = W2[idx];
    __syncthreads();

    // ---- r2 = r1 @ W2^T + b2; log_softmax (one thread per batch) ----
    if (tid < BT){
        const int b = tid;
        float r2[5];
        #pragma unroll
        for (int o = 0; o < 5; o++) r2[o] = b2[o];
        for (int kk = 0; kk < HH; kk++){
            int k = (kk + b*4) & (HH - 1);
            float v = r1_sh[b*HH + k];
            #pragma unroll
            for (int o = 0; o < 5; o++) r2[o] = fmaf(v, w2sh[o*HH + k], r2[o]);
        }
        float m = r2[0];
        #pragma unroll
        for (int o = 1; o < 5; o++) m = fmaxf(m, r2[o]);
        float s = 0.0f;
        #pragma unroll
        for (int o = 0; o < 5; o++) s += __expf(r2[o] - m);
        float l = m + __logf(s);
        #pragma unroll
        for (int o = 0; o < 5; o++)
            out[(size_t)(b0 + b)*5 + o] = r2[o] - l;
    }
}

extern "C" void kernel_launch(void* const* d_in, const int* in_sizes, int n_in,
                              void* d_out, int out_size){
    const float* x   = (const float*)d_in[0];
    const float* Wih = (const float*)d_in[1];
    const float* Whh = (const float*)d_in[2];
    const float* bih = (const float*)d_in[3];
    const float* bhh = (const float*)d_in[4];
    const float* W1  = (const float*)d_in[5];
    const float* b1  = (const float*)d_in[6];
    const float* W2  = (const float*)d_in[7];
    const float* b2  = (const float*)d_in[8];
    float* out = (float*)d_out;

    prep_kernel<<<128, 256>>>(Whh, W1);

    cudaFuncSetAttribute(lstm_kernel,
                         cudaFuncAttributeMaxDynamicSharedMemorySize, SMEM_BYTES);
    lstm_kernel<<<NCTA, NTHR, SMEM_BYTES>>>(x, Wih, bih, bhh, b1, W2, b2, out);
}

// round 9
// speedup vs baseline: 1.1065x; 1.1065x over previous
#include <cuda_runtime.h>
#include <cuda_fp16.h>
#include <cstdint>

#define TT 140
#define HH 128
#define BT 32
#define NCTA 128
#define NTHR 256

#define WSTRIDE 136                    // halfs per weight row (272 B, conflict-free LDSM)
#define WROWS   640                    // 512 gate rows + 128 W1 rows
#define WBYTES  (WROWS*WSTRIDE*2)      // 174080
#define HSTRIDE 40                     // halfs per h row (80 B, conflict-free)
#define HBYTES  (HH*HSTRIDE*2)         // 10240
#define OFF_W   0
#define OFF_H   WBYTES                 // two h buffers
#define OFF_X   (OFF_H + 2*HBYTES)     // x_sh [t][b] f32; reused as r1_sh in tail
#define OFF_F   (OFF_X + TT*BT*4)      // 8 chunk flags
#define SMEM_BYTES (OFF_F + 64)        // 212544

// f16 weights, padded layout: rows 0..511 = W_hh (gate-major), rows 512..639 = W1
__device__ __align__(16) unsigned short g_W16[WROWS*WSTRIDE];

// ---------------- helpers ----------------
__device__ __forceinline__ uint32_t smem_u32(const void* p){
    uint32_t a;
    asm("{ .reg .u64 t; cvta.to.shared.u64 t, %1; cvt.u32.u64 %0, t; }"
        : "=r"(a) : "l"(p));
    return a;
}
__device__ __forceinline__ void cp_async16(void* s, const void* g){
    unsigned a = smem_u32(s);
    asm volatile("cp.async.cg.shared.global [%0],[%1],16;" :: "r"(a), "l"(g));
}
__device__ __forceinline__ void ldsm4(uint32_t* r, uint32_t addr){
    asm volatile("ldmatrix.sync.aligned.m8n8.x4.shared.b16 {%0,%1,%2,%3},[%4];"
        : "=r"(r[0]),"=r"(r[1]),"=r"(r[2]),"=r"(r[3]) : "r"(addr));
}
__device__ __forceinline__ void ldsm4t(uint32_t* r, uint32_t addr){
    asm volatile("ldmatrix.sync.aligned.m8n8.x4.trans.shared.b16 {%0,%1,%2,%3},[%4];"
        : "=r"(r[0]),"=r"(r[1]),"=r"(r[2]),"=r"(r[3]) : "r"(addr));
}
__device__ __forceinline__ void mma16816(float* d, const uint32_t* a,
                                         uint32_t b0, uint32_t b1){
    asm volatile("mma.sync.aligned.m16n8k16.row.col.f32.f16.f16.f32 "
        "{%0,%1,%2,%3},{%4,%5,%6,%7},{%8,%9},{%0,%1,%2,%3};"
        : "+f"(d[0]),"+f"(d[1]),"+f"(d[2]),"+f"(d[3])
        : "r"(a[0]),"r"(a[1]),"r"(a[2]),"r"(a[3]),"r"(b0),"r"(b1));
}
__device__ __forceinline__ float mufu_tanh(float x){
    float r;
    asm("tanh.approx.f32 %0,%1;" : "=f"(r) : "f"(x));
    return r;
}
__device__ __forceinline__ float fast_sigmoid(float x){
    return fmaf(0.5f, mufu_tanh(0.5f * x), 0.5f);
}
__device__ __forceinline__ uint32_t ld_acq(uint32_t a){
    uint32_t v;
    asm volatile("ld.acquire.cta.shared.u32 %0,[%1];" : "=r"(v) : "r"(a) : "memory");
    return v;
}
__device__ __forceinline__ void st_rel(uint32_t a, uint32_t v){
    asm volatile("st.release.cta.shared.u32 [%0],%1;" :: "r"(a), "r"(v) : "memory");
}
__device__ __forceinline__ void spin_wait(uint32_t addr, uint32_t want){
    if (ld_acq(addr) >= want) return;
    while (ld_acq(addr) < want)
        asm volatile("nanosleep.u32 40;");
}

// ---------------- prep: convert weights to f16 padded layout ----------------
__global__ void prep_kernel(const float* __restrict__ Whh,
                            const float* __restrict__ W1){
    int i = blockIdx.x * blockDim.x + threadIdx.x;
    int stride = gridDim.x * blockDim.x;
    for (int idx = i; idx < WROWS*HH; idx += stride){
        int row = idx >> 7, k = idx & 127;
        float v = (row < 512) ? Whh[row*HH + k] : W1[(row - 512)*HH + k];
        __half hv = __float2half_rn(v);
        g_W16[row*WSTRIDE + k] = *(unsigned short*)&hv;
    }
}

// ---------------- main persistent LSTM kernel ----------------
__global__ __launch_bounds__(NTHR, 1)
void lstm_kernel(const float* __restrict__ x,
                 const float* __restrict__ Wih,
                 const float* __restrict__ bih,
                 const float* __restrict__ bhh,
                 const float* __restrict__ b1,
                 const float* __restrict__ W2,
                 const float* __restrict__ b2,
                 float* __restrict__ out){
    extern __shared__ char sm[];
    const uint32_t smb = smem_u32(sm);
    const int tid  = threadIdx.x;
    const int lane = tid & 31;
    const int w    = tid >> 5;          // warp 0..7, owns units 16w..16w+15
    const int b0   = blockIdx.x * BT;
    float* x_sh = (float*)(sm + OFF_X);
    const uint32_t flagb = smb + OFF_F;

    // ---- stage W (f16) via cp.async; x; zero h buffer 0; init flags ----
    for (int i = tid*16; i < WBYTES; i += NTHR*16)
        cp_async16(sm + OFF_W + i, (const char*)g_W16 + i);
    asm volatile("cp.async.commit_group;" ::: "memory");
    for (int idx = tid; idx < TT*BT; idx += NTHR){
        int t = idx >> 5, b = idx & 31;
        x_sh[t*32 + b] = x[(size_t)(b0 + b)*TT + t];
    }
    for (int i = tid; i < HBYTES/4; i += NTHR)
        ((float*)(sm + OFF_H))[i] = 0.0f;
    if (tid < 8) ((uint32_t*)(sm + OFF_F))[tid] = 1u;
    asm volatile("cp.async.wait_group 0;" ::: "memory");
    __syncthreads();

    // ---- per-thread constants ----
    const int u0 = 16*w + (lane >> 2);
    const int u1 = u0 + 8;
    float wi[4][2], bs[4][2];
    #pragma unroll
    for (int g = 0; g < 4; g++){
        wi[g][0] = Wih[g*HH + u0];
        wi[g][1] = Wih[g*HH + u1];
        bs[g][0] = bih[g*HH + u0] + bhh[g*HH + u0];
        bs[g][1] = bih[g*HH + u1] + bhh[g*HH + u1];
    }
    float c0[8], c1[8];
    #pragma unroll
    for (int i = 0; i < 8; i++){ c0[i] = 0.0f; c1[i] = 0.0f; }

    // ldmatrix address bases
    uint32_t Abase[4];
    #pragma unroll
    for (int mt = 0; mt < 4; mt++)
        Abase[mt] = smb + OFF_W +
            (uint32_t)(((mt*128 + 16*w + (lane & 15))*WSTRIDE + (lane >> 4)*8) * 2);
    const uint32_t AbaseT = smb + OFF_W +
            (uint32_t)(((512 + 16*w + (lane & 15))*WSTRIDE + (lane >> 4)*8) * 2);
    const uint32_t Brow = (uint32_t)((lane & 7) + ((lane >> 3) & 1)*8);
    const uint32_t Bb0  = smb + OFF_H + Brow*(HSTRIDE*2) + (uint32_t)((lane >> 4)*8)*2;
    const uint32_t Bb1  = Bb0 + 32;     // n0 = 16
    const int bq = 2*(lane & 3);        // batch pair within n8 tile

    uint32_t bsel = 0;                  // byte offset of current read h buffer
    for (int t = 0; t < TT; t++){
        // init accumulators with bias + x_t * w_in
        float acc[4][4][4];
        float xv[4][2];
        #pragma unroll
        for (int nt = 0; nt < 4; nt++){
            xv[nt][0] = x_sh[t*32 + 8*nt + bq];
            xv[nt][1] = x_sh[t*32 + 8*nt + bq + 1];
        }
        #pragma unroll
        for (int mt = 0; mt < 4; mt++)
            #pragma unroll
            for (int nt = 0; nt < 4; nt++){
                acc[mt][nt][0] = fmaf(xv[nt][0], wi[mt][0], bs[mt][0]);
                acc[mt][nt][1] = fmaf(xv[nt][1], wi[mt][0], bs[mt][0]);
                acc[mt][nt][2] = fmaf(xv[nt][0], wi[mt][1], bs[mt][1]);
                acc[mt][nt][3] = fmaf(xv[nt][1], wi[mt][1], bs[mt][1]);
            }

        // gates += W @ h (K=128, 8 chunks, rotated start = own chunk)
        const uint32_t Bc0 = Bb0 + bsel, Bc1 = Bb1 + bsel;
        const uint32_t want = (uint32_t)(t + 1);
        #pragma unroll
        for (int i = 0; i < 8; i++){
            const int kc = (w + i) & 7;
            spin_wait(flagb + kc*4, want);
            uint32_t bfr0[4], bfr1[4];
            ldsm4t(bfr0, Bc0 + kc*(16*HSTRIDE*2));
            ldsm4t(bfr1, Bc1 + kc*(16*HSTRIDE*2));
            #pragma unroll
            for (int mt = 0; mt < 4; mt++){
                uint32_t a[4];
                ldsm4(a, Abase[mt] + kc*32);
                mma16816(acc[mt][0], a, bfr0[0], bfr0[1]);
                mma16816(acc[mt][1], a, bfr0[2], bfr0[3]);
                mma16816(acc[mt][2], a, bfr1[0], bfr1[1]);
                mma16816(acc[mt][3], a, bfr1[2], bfr1[3]);
            }
        }

        // elementwise LSTM update; write h chunk w to other buffer
        const uint32_t wsel = bsel ^ HBYTES;
        #pragma unroll
        for (int nt = 0; nt < 4; nt++){
            float hv0[2], hv1[2];
            #pragma unroll
            for (int j = 0; j < 2; j++){
                int ci = nt*2 + j;
                {   // unit u0
                    float iv = fast_sigmoid(acc[0][nt][j]);
                    float fv = fast_sigmoid(acc[1][nt][j]);
                    float gv = mufu_tanh   (acc[2][nt][j]);
                    float ov = fast_sigmoid(acc[3][nt][j]);
                    float cv = fv * c0[ci] + iv * gv;
                    c0[ci] = cv;
                    hv0[j] = ov * mufu_tanh(cv);
                }
                {   // unit u1
                    float iv = fast_sigmoid(acc[0][nt][2+j]);
                    float fv = fast_sigmoid(acc[1][nt][2+j]);
                    float gv = mufu_tanh   (acc[2][nt][2+j]);
                    float ov = fast_sigmoid(acc[3][nt][2+j]);
                    float cv = fv * c1[ci] + iv * gv;
                    c1[ci] = cv;
                    hv1[j] = ov * mufu_tanh(cv);
                }
            }
            int boff = (8*nt + bq)*2;
            *(half2*)(sm + OFF_H + wsel + u0*(HSTRIDE*2) + boff) =
                __floats2half2_rn(hv0[0], hv0[1]);
            *(half2*)(sm + OFF_H + wsel + u1*(HSTRIDE*2) + boff) =
                __floats2half2_rn(hv1[0], hv1[1]);
        }
        __syncwarp();
        if (lane == 0) st_rel(flagb + w*4, (uint32_t)(t + 2));
        bsel = wsel;
    }
    // final h is in buffer bsel (flags reach TT+1 when each chunk is ready)

    // ---- MLP head: r1 = relu(W1 @ h + b1) via the same MMA path ----
    float racc[4][4];
    {
        float bv0 = b1[u0], bv1 = b1[u1];
        #pragma unroll
        for (int nt = 0; nt < 4; nt++){
            racc[nt][0] = bv0; racc[nt][1] = bv0;
            racc[nt][2] = bv1; racc[nt][3] = bv1;
        }
    }
    {
        const uint32_t Bc0 = Bb0 + bsel, Bc1 = Bb1 + bsel;
        const uint32_t want = (uint32_t)(TT + 1);
        #pragma unroll
        for (int i = 0; i < 8; i++){
            const int kc = (w + i) & 7;
            spin_wait(flagb + kc*4, want);
            uint32_t bfr0[4], bfr1[4];
            ldsm4t(bfr0, Bc0 + kc*(16*HSTRIDE*2));
            ldsm4t(bfr1, Bc1 + kc*(16*HSTRIDE*2));
            uint32_t a[4];
            ldsm4(a, AbaseT + kc*32);
            mma16816(racc[0], a, bfr0[0], bfr0[1]);
            mma16816(racc[1], a, bfr0[2], bfr0[3]);
            mma16816(racc[2], a, bfr1[0], bfr1[1]);
            mma16816(racc[3], a, bfr1[2], bfr1[3]);
        }
    }
    __syncthreads();            // everyone past step loop; reuse x_sh as r1_sh
    float* r1_sh = (float*)(sm + OFF_X);   // [b][n] f32
    #pragma unroll
    for (int nt = 0; nt < 4; nt++)
        #pragma unroll
        for (int j = 0; j < 2; j++){
            int b = 8*nt + bq + j;
            r1_sh[b*HH + u0] = fmaxf(racc[nt][j],     0.0f);
            r1_sh[b*HH + u1] = fmaxf(racc[nt][2 + j], 0.0f);
        }
    __syncthreads();
    // stage W2 (5x128 f32) into h region (done with h)
    float* w2sh = (float*)(sm + OFF_H);
    for (int idx = tid; idx < 5*HH; idx += NTHR) w2sh[idx] = W2[idx];
    __syncthreads();

    // ---- r2 = r1 @ W2^T + b2; log_softmax (one thread per batch) ----
    if (tid < BT){
        const int b = tid;
        float r2[5];
        #pragma unroll
        for (int o = 0; o < 5; o++) r2[o] = b2[o];
        for (int kk = 0; kk < HH; kk++){
            int k = (kk + b*4) & (HH - 1);
            float v = r1_sh[b*HH + k];
            #pragma unroll
            for (int o = 0; o < 5; o++) r2[o] = fmaf(v, w2sh[o*HH + k], r2[o]);
        }
        float m = r2[0];
        #pragma unroll
        for (int o = 1; o < 5; o++) m = fmaxf(m, r2[o]);
        float s = 0.0f;
        #pragma unroll
        for (int o = 0; o < 5; o++) s += __expf(r2[o] - m);
        float l = m + __logf(s);
        #pragma unroll
        for (int o = 0; o < 5; o++)
            out[(size_t)(b0 + b)*5 + o] = r2[o] - l;
    }
}

extern "C" void kernel_launch(void* const* d_in, const int* in_sizes, int n_in,
                              void* d_out, int out_size){
    const float* x   = (const float*)d_in[0];
    const float* Wih = (const float*)d_in[1];
    const float* Whh = (const float*)d_in[2];
    const float* bih = (const float*)d_in[3];
    const float* bhh = (const float*)d_in[4];
    const float* W1  = (const float*)d_in[5];
    const float* b1  = (const float*)d_in[6];
    const float* W2  = (const float*)d_in[7];
    const float* b2  = (const float*)d_in[8];
    float* out = (float*)d_out;

    prep_kernel<<<128, 256>>>(Whh, W1);

    cudaFuncSetAttribute(lstm_kernel,
                         cudaFuncAttributeMaxDynamicSharedMemorySize, SMEM_BYTES);
    lstm_kernel<<<NCTA, NTHR, SMEM_BYTES>>>(x, Wih, bih, bhh, b1, W2, b2, out);
}

// round 11
// speedup vs baseline: 1.1939x; 1.0790x over previous
#include <cuda_runtime.h>
#include <cuda_fp16.h>
#include <cstdint>

#define TT 140
#define HH 128
#define BT 32
#define NCTA 128
#define NTHR 256

#define WSTRIDE 136                    // halfs per weight row (272 B, conflict-free LDSM)
#define WROWS   640                    // 512 gate rows + 128 W1 rows
#define WBYTES  (WROWS*WSTRIDE*2)      // 174080
#define HSTRIDE 40                     // halfs per h row (80 B, conflict-free)
#define HBYTES  (HH*HSTRIDE*2)         // 10240
#define CHB     (16*HSTRIDE*2)         // bytes per 16-row h chunk
#define OFF_W   0
#define OFF_H   WBYTES                 // two h buffers
#define OFF_X   (OFF_H + 2*HBYTES)     // x_sh [t][b] f32; reused as r1_sh in tail
#define OFF_F   (OFF_X + TT*BT*4)      // 8 chunk flags
#define SMEM_BYTES (OFF_F + 64)        // 212544

// f16 weights, padded layout: rows 0..511 = W_hh (gate-major), rows 512..639 = W1
__device__ __align__(16) unsigned short g_W16[WROWS*WSTRIDE];

// ---------------- helpers ----------------
__device__ __forceinline__ uint32_t smem_u32(const void* p){
    uint32_t a;
    asm("{ .reg .u64 t; cvta.to.shared.u64 t, %1; cvt.u32.u64 %0, t; }"
        : "=r"(a) : "l"(p));
    return a;
}
__device__ __forceinline__ void cp_async16(void* s, const void* g){
    unsigned a = smem_u32(s);
    asm volatile("cp.async.cg.shared.global [%0],[%1],16;" :: "r"(a), "l"(g));
}
__device__ __forceinline__ void ldsm4(uint32_t* r, uint32_t addr){
    asm volatile("ldmatrix.sync.aligned.m8n8.x4.shared.b16 {%0,%1,%2,%3},[%4];"
        : "=r"(r[0]),"=r"(r[1]),"=r"(r[2]),"=r"(r[3]) : "r"(addr));
}
__device__ __forceinline__ void ldsm4t(uint32_t* r, uint32_t addr){
    asm volatile("ldmatrix.sync.aligned.m8n8.x4.trans.shared.b16 {%0,%1,%2,%3},[%4];"
        : "=r"(r[0]),"=r"(r[1]),"=r"(r[2]),"=r"(r[3]) : "r"(addr));
}
__device__ __forceinline__ void mma16816(float* d, const uint32_t* a,
                                         uint32_t b0, uint32_t b1){
    asm volatile("mma.sync.aligned.m16n8k16.row.col.f32.f16.f16.f32 "
        "{%0,%1,%2,%3},{%4,%5,%6,%7},{%8,%9},{%0,%1,%2,%3};"
        : "+f"(d[0]),"+f"(d[1]),"+f"(d[2]),"+f"(d[3])
        : "r"(a[0]),"r"(a[1]),"r"(a[2]),"r"(a[3]),"r"(b0),"r"(b1));
}
__device__ __forceinline__ __half2 ht2_tanh(__half2 x){
    uint32_t xu = *(uint32_t*)&x, r;
    asm("tanh.approx.f16x2 %0,%1;" : "=r"(r) : "r"(xu));
    return *(__half2*)&r;
}
__device__ __forceinline__ __half2 ht2_sig(__half2 x, __half2 h05){
    return __hfma2(ht2_tanh(__hmul2(x, h05)), h05, h05);
}
__device__ __forceinline__ uint32_t ld_acq(uint32_t a){
    uint32_t v;
    asm volatile("ld.acquire.cta.shared.u32 %0,[%1];" : "=r"(v) : "r"(a) : "memory");
    return v;
}
__device__ __forceinline__ void st_rel(uint32_t a, uint32_t v){
    asm volatile("st.release.cta.shared.u32 [%0],%1;" :: "r"(a), "r"(v) : "memory");
}
// one warp-parallel wait for all 8 chunk flags
__device__ __forceinline__ void wait_all_flags(uint32_t flagb, uint32_t want, int lane){
    uint32_t v = (lane < 8) ? ld_acq(flagb + lane*4) : want;
    while (!__all_sync(0xffffffffu, v >= want)){
        asm volatile("nanosleep.u32 20;");
        v = (lane < 8) ? ld_acq(flagb + lane*4) : want;
    }
    __syncwarp();
}

// ---------------- prep: convert weights to f16 padded layout ----------------
__global__ void prep_kernel(const float* __restrict__ Whh,
                            const float* __restrict__ W1){
    int i = blockIdx.x * blockDim.x + threadIdx.x;
    int stride = gridDim.x * blockDim.x;
    for (int idx = i; idx < WROWS*HH; idx += stride){
        int row = idx >> 7, k = idx & 127;
        float v = (row < 512) ? Whh[row*HH + k] : W1[(row - 512)*HH + k];
        __half hv = __float2half_rn(v);
        g_W16[row*WSTRIDE + k] = *(unsigned short*)&hv;
    }
}

// ---------------- main persistent LSTM kernel ----------------
__global__ __launch_bounds__(NTHR, 1)
void lstm_kernel(const float* __restrict__ x,
                 const float* __restrict__ Wih,
                 const float* __restrict__ bih,
                 const float* __restrict__ bhh,
                 const float* __restrict__ b1,
                 const float* __restrict__ W2,
                 const float* __restrict__ b2,
                 float* __restrict__ out){
    extern __shared__ char sm[];
    const uint32_t smb = smem_u32(sm);
    const int tid  = threadIdx.x;
    const int lane = tid & 31;
    const int w    = tid >> 5;          // warp 0..7, owns units 16w..16w+15
    const int b0   = blockIdx.x * BT;
    float* x_sh = (float*)(sm + OFF_X);
    const uint32_t flagb = smb + OFF_F;
    const __half2 h05 = __float2half2_rn(0.5f);

    // ---- stage W (f16) via cp.async; x; zero h buffer 0; init flags ----
    for (int i = tid*16; i < WBYTES; i += NTHR*16)
        cp_async16(sm + OFF_W + i, (const char*)g_W16 + i);
    asm volatile("cp.async.commit_group;" ::: "memory");
    for (int idx = tid; idx < TT*BT; idx += NTHR){
        int t = idx >> 5, b = idx & 31;
        x_sh[t*32 + b] = x[(size_t)(b0 + b)*TT + t];
    }
    for (int i = tid; i < HBYTES/4; i += NTHR)
        ((float*)(sm + OFF_H))[i] = 0.0f;
    if (tid < 8) ((uint32_t*)(sm + OFF_F))[tid] = 1u;
    asm volatile("cp.async.wait_group 0;" ::: "memory");
    __syncthreads();

    // ---- per-thread constants ----
    const int u0 = 16*w + (lane >> 2);
    const int u1 = u0 + 8;
    float wi[4][2], bs[4][2];
    #pragma unroll
    for (int g = 0; g < 4; g++){
        wi[g][0] = Wih[g*HH + u0];
        wi[g][1] = Wih[g*HH + u1];
        bs[g][0] = bih[g*HH + u0] + bhh[g*HH + u0];
        bs[g][1] = bih[g*HH + u1] + bhh[g*HH + u1];
    }
    __half2 ch0[4], ch1[4];
    #pragma unroll
    for (int i = 0; i < 4; i++){
        ch0[i] = __float2half2_rn(0.0f);
        ch1[i] = __float2half2_rn(0.0f);
    }

    // ldmatrix address bases
    uint32_t Abase[4];
    #pragma unroll
    for (int mt = 0; mt < 4; mt++)
        Abase[mt] = smb + OFF_W +
            (uint32_t)(((mt*128 + 16*w + (lane & 15))*WSTRIDE + (lane >> 4)*8) * 2);
    const uint32_t AbaseT = smb + OFF_W +
            (uint32_t)(((512 + 16*w + (lane & 15))*WSTRIDE + (lane >> 4)*8) * 2);
    const uint32_t Brow = (uint32_t)((lane & 7) + ((lane >> 3) & 1)*8);
    const uint32_t Bb0  = smb + OFF_H + Brow*(HSTRIDE*2) + (uint32_t)((lane >> 4)*8)*2;
    const uint32_t Bb1  = Bb0 + 32;     // n0 = 16
    const int bq = 2*(lane & 3);        // batch pair within n8 tile

    // ---- cache A fragments for first 4 chunks of this warp's rotation ----
    uint32_t Areg[4][4][4];
    #pragma unroll
    for (int i = 0; i < 4; i++){
        const int kc = (w + i) & 7;
        #pragma unroll
        for (int mt = 0; mt < 4; mt++)
            ldsm4(Areg[i][mt], Abase[mt] + kc*32);
    }

    uint32_t bsel = 0;                  // byte offset of current read h buffer
    for (int t = 0; t < TT; t++){
        // init accumulators with bias + x_t * w_in
        float acc[4][4][4];
        float xv[4][2];
        #pragma unroll
        for (int nt = 0; nt < 4; nt++){
            xv[nt][0] = x_sh[t*32 + 8*nt + bq];
            xv[nt][1] = x_sh[t*32 + 8*nt + bq + 1];
        }
        #pragma unroll
        for (int mt = 0; mt < 4; mt++)
            #pragma unroll
            for (int nt = 0; nt < 4; nt++){
                acc[mt][nt][0] = fmaf(xv[nt][0], wi[mt][0], bs[mt][0]);
                acc[mt][nt][1] = fmaf(xv[nt][1], wi[mt][0], bs[mt][0]);
                acc[mt][nt][2] = fmaf(xv[nt][0], wi[mt][1], bs[mt][1]);
                acc[mt][nt][3] = fmaf(xv[nt][1], wi[mt][1], bs[mt][1]);
            }

        const uint32_t Bc0 = Bb0 + bsel, Bc1 = Bb1 + bsel;
        const uint32_t want = (uint32_t)(t + 1);

        // chunk i=0 (kc = w): own chunk, flag set by this warp — no wait
        {
            const int kc = w;
            uint32_t bfr0[4], bfr1[4];
            ldsm4t(bfr0, Bc0 + kc*CHB);
            ldsm4t(bfr1, Bc1 + kc*CHB);
            #pragma unroll
            for (int mt = 0; mt < 4; mt++){
                mma16816(acc[mt][0], Areg[0][mt], bfr0[0], bfr0[1]);
                mma16816(acc[mt][1], Areg[0][mt], bfr0[2], bfr0[3]);
                mma16816(acc[mt][2], Areg[0][mt], bfr1[0], bfr1[1]);
                mma16816(acc[mt][3], Areg[0][mt], bfr1[2], bfr1[3]);
            }
        }
        // single warp-parallel wait for all producers of this step's h
        wait_all_flags(flagb, want, lane);

        // chunks i=1..3: cached A
        #pragma unroll
        for (int i = 1; i < 4; i++){
            const int kc = (w + i) & 7;
            uint32_t bfr0[4], bfr1[4];
            ldsm4t(bfr0, Bc0 + kc*CHB);
            ldsm4t(bfr1, Bc1 + kc*CHB);
            #pragma unroll
            for (int mt = 0; mt < 4; mt++){
                mma16816(acc[mt][0], Areg[i][mt], bfr0[0], bfr0[1]);
                mma16816(acc[mt][1], Areg[i][mt], bfr0[2], bfr0[3]);
                mma16816(acc[mt][2], Areg[i][mt], bfr1[0], bfr1[1]);
                mma16816(acc[mt][3], Areg[i][mt], bfr1[2], bfr1[3]);
            }
        }
        // chunks i=4..7: stream A from smem
        #pragma unroll
        for (int i = 4; i < 8; i++){
            const int kc = (w + i) & 7;
            uint32_t bfr0[4], bfr1[4];
            ldsm4t(bfr0, Bc0 + kc*CHB);
            ldsm4t(bfr1, Bc1 + kc*CHB);
            #pragma unroll
            for (int mt = 0; mt < 4; mt++){
                uint32_t a[4];
                ldsm4(a, Abase[mt] + kc*32);
                mma16816(acc[mt][0], a, bfr0[0], bfr0[1]);
                mma16816(acc[mt][1], a, bfr0[2], bfr0[3]);
                mma16816(acc[mt][2], a, bfr1[0], bfr1[1]);
                mma16816(acc[mt][3], a, bfr1[2], bfr1[3]);
            }
        }

        // f16x2 LSTM elementwise update; write h chunk w to other buffer
        const uint32_t wsel = bsel ^ HBYTES;
        #pragma unroll
        for (int nt = 0; nt < 4; nt++){
            const int boff = (8*nt + bq)*2;
            {   // unit u0, batch pair
                __half2 gi = __floats2half2_rn(acc[0][nt][0], acc[0][nt][1]);
                __half2 gf = __floats2half2_rn(acc[1][nt][0], acc[1][nt][1]);
                __half2 gg = __floats2half2_rn(acc[2][nt][0], acc[2][nt][1]);
                __half2 go = __floats2half2_rn(acc[3][nt][0], acc[3][nt][1]);
                __half2 iv = ht2_sig(gi, h05);
                __half2 fv = ht2_sig(gf, h05);
                __half2 gv = ht2_tanh(gg);
                __half2 ov = ht2_sig(go, h05);
                __half2 cv = __hfma2(fv, ch0[nt], __hmul2(iv, gv));
                ch0[nt] = cv;
                __half2 hv = __hmul2(ov, ht2_tanh(cv));
                *(__half2*)(sm + OFF_H + wsel + u0*(HSTRIDE*2) + boff) = hv;
            }
            {   // unit u1, batch pair
                __half2 gi = __floats2half2_rn(acc[0][nt][2], acc[0][nt][3]);
                __half2 gf = __floats2half2_rn(acc[1][nt][2], acc[1][nt][3]);
                __half2 gg = __floats2half2_rn(acc[2][nt][2], acc[2][nt][3]);
                __half2 go = __floats2half2_rn(acc[3][nt][2], acc[3][nt][3]);
                __half2 iv = ht2_sig(gi, h05);
                __half2 fv = ht2_sig(gf, h05);
                __half2 gv = ht2_tanh(gg);
                __half2 ov = ht2_sig(go, h05);
                __half2 cv = __hfma2(fv, ch1[nt], __hmul2(iv, gv));
                ch1[nt] = cv;
                __half2 hv = __hmul2(ov, ht2_tanh(cv));
                *(__half2*)(sm + OFF_H + wsel + u1*(HSTRIDE*2) + boff) = hv;
            }
        }
        __syncwarp();
        if (lane == 0) st_rel(flagb + w*4, (uint32_t)(t + 2));
        bsel = wsel;
    }
    // final h is in buffer bsel (flags reach TT+1 when each chunk is ready)

    // ---- MLP head: r1 = relu(W1 @ h + b1) via the same MMA path ----
    float racc[4][4];
    {
        float bv0 = b1[u0], bv1 = b1[u1];
        #pragma unroll
        for (int nt = 0; nt < 4; nt++){
            racc[nt][0] = bv0; racc[nt][1] = bv0;
            racc[nt][2] = bv1; racc[nt][3] = bv1;
        }
    }
    {
        wait_all_flags(flagb, (uint32_t)(TT + 1), lane);
        const uint32_t Bc0 = Bb0 + bsel, Bc1 = Bb1 + bsel;
        #pragma unroll
        for (int kc = 0; kc < 8; kc++){
            uint32_t bfr0[4], bfr1[4];
            ldsm4t(bfr0, Bc0 + kc*CHB);
            ldsm4t(bfr1, Bc1 + kc*CHB);
            uint32_t a[4];
            ldsm4(a, AbaseT + kc*32);
            mma16816(racc[0], a, bfr0[0], bfr0[1]);
            mma16816(racc[1], a, bfr0[2], bfr0[3]);
            mma16816(racc[2], a, bfr1[0], bfr1[1]);
            mma16816(racc[3], a, bfr1[2], bfr1[3]);
        }
    }
    __syncthreads();            // everyone past step loop; reuse x_sh as r1_sh
    float* r1_sh = (float*)(sm + OFF_X);   // [b][n] f32
    #pragma unroll
    for (int nt = 0; nt < 4; nt++)
        #pragma unroll
        for (int j = 0; j < 2; j++){
            int b = 8*nt + bq + j;
            r1_sh[b*HH + u0] = fmaxf(racc[nt][j],     0.0f);
            r1_sh[b*HH + u1] = fmaxf(racc[nt][2 + j], 0.0f);
        }
    __syncthreads();
    // stage W2 (5x128 f32) into h region (done with h)
    float* w2sh = (float*)(sm + OFF_H);
    for (int idx = tid; idx < 5*HH; idx += NTHR) w2sh[idx] = W2[idx];
    __syncthreads();

    // ---- r2 = r1 @ W2^T + b2; log_softmax (one thread per batch) ----
    if (tid < BT){
        const int b = tid;
        float r2[5];
        #pragma unroll
        for (int o = 0; o < 5; o++) r2[o] = b2[o];
        for (int kk = 0; kk < HH; kk++){
            int k = (kk + b*4) & (HH - 1);
            float v = r1_sh[b*HH + k];
            #pragma unroll
            for (int o = 0; o < 5; o++) r2[o] = fmaf(v, w2sh[o*HH + k], r2[o]);
        }
        float m = r2[0];
        #pragma unroll
        for (int o = 1; o < 5; o++) m = fmaxf(m, r2[o]);
        float s = 0.0f;
        #pragma unroll
        for (int o = 0; o < 5; o++) s += __expf(r2[o] - m);
        float l = m + __logf(s);
        #pragma unroll
        for (int o = 0; o < 5; o++)
            out[(size_t)(b0 + b)*5 + o] = r2[o] - l;
    }
}

extern "C" void kernel_launch(void* const* d_in, const int* in_sizes, int n_in,
                              void* d_out, int out_size){
    const float* x   = (const float*)d_in[0];
    const float* Wih = (const float*)d_in[1];
    const float* Whh = (const float*)d_in[2];
    const float* bih = (const float*)d_in[3];
    const float* bhh = (const float*)d_in[4];
    const float* W1  = (const float*)d_in[5];
    const float* b1  = (const float*)d_in[6];
    const float* W2  = (const float*)d_in[7];
    const float* b2  = (const float*)d_in[8];
    float* out = (float*)d_out;

    prep_kernel<<<128, 256>>>(Whh, W1);

    cudaFuncSetAttribute(lstm_kernel,
                         cudaFuncAttributeMaxDynamicSharedMemorySize, SMEM_BYTES);
    lstm_kernel<<<NCTA, NTHR, SMEM_BYTES>>>(x, Wih, bih, bhh, b1, W2, b2, out);
}

// round 12
// speedup vs baseline: 1.2646x; 1.0592x over previous
#include <cuda_runtime.h>
#include <cuda_fp16.h>
#include <cstdint>

#define TT 140
#define HH 128
#define BT 32
#define NCTA 128
#define NTHR 256

#define WSTRIDE 136                    // halfs per weight row (272 B, conflict-free LDSM)
#define WROWS   640                    // 512 gate rows + 128 W1 rows
#define WBYTES  (WROWS*WSTRIDE*2)      // 174080
#define HSTRIDE 40                     // halfs per h row (80 B, conflict-free)
#define HBYTES  (HH*HSTRIDE*2)         // 10240
#define CHB     (16*HSTRIDE*2)         // bytes per 16-row h chunk
#define OFF_W   0
#define OFF_H   WBYTES                 // two h buffers
#define OFF_X   (OFF_H + 2*HBYTES)     // x2_sh [t][16] half2; tail reuses as r1_sh f32
#define SMEM_BYTES (OFF_X + TT*BT*4 + 64)   // keep f32-era size (tail r1_sh needs 16KB)
#define OFF_F   (OFF_X + TT*BT*4)      // 8 chunk flags

// f16 weights, padded layout: rows 0..511 = W_hh (gate-major), rows 512..639 = W1
__device__ __align__(16) unsigned short g_W16[WROWS*WSTRIDE];

// ---------------- helpers ----------------
__device__ __forceinline__ uint32_t smem_u32(const void* p){
    uint32_t a;
    asm("{ .reg .u64 t; cvta.to.shared.u64 t, %1; cvt.u32.u64 %0, t; }"
        : "=r"(a) : "l"(p));
    return a;
}
__device__ __forceinline__ void cp_async16(void* s, const void* g){
    unsigned a = smem_u32(s);
    asm volatile("cp.async.cg.shared.global [%0],[%1],16;" :: "r"(a), "l"(g));
}
__device__ __forceinline__ void ldsm4(uint32_t* r, uint32_t addr){
    asm volatile("ldmatrix.sync.aligned.m8n8.x4.shared.b16 {%0,%1,%2,%3},[%4];"
        : "=r"(r[0]),"=r"(r[1]),"=r"(r[2]),"=r"(r[3]) : "r"(addr));
}
__device__ __forceinline__ void ldsm4t(uint32_t* r, uint32_t addr){
    asm volatile("ldmatrix.sync.aligned.m8n8.x4.trans.shared.b16 {%0,%1,%2,%3},[%4];"
        : "=r"(r[0]),"=r"(r[1]),"=r"(r[2]),"=r"(r[3]) : "r"(addr));
}
// f16-accumulator MMA: D,C packed half2 (d0 = rows r, d1 = rows r+8)
__device__ __forceinline__ void mma16816h(uint32_t& d0, uint32_t& d1,
                                          const uint32_t* a,
                                          uint32_t b0, uint32_t b1){
    asm volatile("mma.sync.aligned.m16n8k16.row.col.f16.f16.f16.f16 "
        "{%0,%1},{%2,%3,%4,%5},{%6,%7},{%0,%1};"
        : "+r"(d0),"+r"(d1)
        : "r"(a[0]),"r"(a[1]),"r"(a[2]),"r"(a[3]),"r"(b0),"r"(b1));
}
// f32-accumulator MMA (used once in the MLP head)
__device__ __forceinline__ void mma16816(float* d, const uint32_t* a,
                                         uint32_t b0, uint32_t b1){
    asm volatile("mma.sync.aligned.m16n8k16.row.col.f32.f16.f16.f32 "
        "{%0,%1,%2,%3},{%4,%5,%6,%7},{%8,%9},{%0,%1,%2,%3};"
        : "+f"(d[0]),"+f"(d[1]),"+f"(d[2]),"+f"(d[3])
        : "r"(a[0]),"r"(a[1]),"r"(a[2]),"r"(a[3]),"r"(b0),"r"(b1));
}
__device__ __forceinline__ __half2 ht2_tanh(__half2 x){
    uint32_t xu = *(uint32_t*)&x, r;
    asm("tanh.approx.f16x2 %0,%1;" : "=r"(r) : "r"(xu));
    return *(__half2*)&r;
}
__device__ __forceinline__ __half2 ht2_sig(__half2 x, __half2 h05){
    return __hfma2(ht2_tanh(__hmul2(x, h05)), h05, h05);
}
__device__ __forceinline__ uint32_t ld_acq(uint32_t a){
    uint32_t v;
    asm volatile("ld.acquire.cta.shared.u32 %0,[%1];" : "=r"(v) : "r"(a) : "memory");
    return v;
}
__device__ __forceinline__ void st_rel(uint32_t a, uint32_t v){
    asm volatile("st.release.cta.shared.u32 [%0],%1;" :: "r"(a), "r"(v) : "memory");
}
__device__ __forceinline__ void wait_all_flags(uint32_t flagb, uint32_t want, int lane){
    uint32_t v = (lane < 8) ? ld_acq(flagb + lane*4) : want;
    while (!__all_sync(0xffffffffu, v >= want)){
        asm volatile("nanosleep.u32 20;");
        v = (lane < 8) ? ld_acq(flagb + lane*4) : want;
    }
    __syncwarp();
}

// ---------------- prep: convert weights to f16 padded layout ----------------
__global__ void prep_kernel(const float* __restrict__ Whh,
                            const float* __restrict__ W1){
    int i = blockIdx.x * blockDim.x + threadIdx.x;
    int stride = gridDim.x * blockDim.x;
    for (int idx = i; idx < WROWS*HH; idx += stride){
        int row = idx >> 7, k = idx & 127;
        float v = (row < 512) ? Whh[row*HH + k] : W1[(row - 512)*HH + k];
        __half hv = __float2half_rn(v);
        g_W16[row*WSTRIDE + k] = *(unsigned short*)&hv;
    }
}

// ---------------- main persistent LSTM kernel ----------------
__global__ __launch_bounds__(NTHR, 1)
void lstm_kernel(const float* __restrict__ x,
                 const float* __restrict__ Wih,
                 const float* __restrict__ bih,
                 const float* __restrict__ bhh,
                 const float* __restrict__ b1,
                 const float* __restrict__ W2,
                 const float* __restrict__ b2,
                 float* __restrict__ out){
    extern __shared__ char sm[];
    const uint32_t smb = smem_u32(sm);
    const int tid  = threadIdx.x;
    const int lane = tid & 31;
    const int w    = tid >> 5;          // warp 0..7, owns units 16w..16w+15
    const int b0   = blockIdx.x * BT;
    __half2* x2_sh = (__half2*)(sm + OFF_X);   // [t][16] batch pairs
    const uint32_t flagb = smb + OFF_F;
    const __half2 h05 = __float2half2_rn(0.5f);

    // ---- stage W (f16) via cp.async; x (as half2 pairs); zero h buffer 0 ----
    for (int i = tid*16; i < WBYTES; i += NTHR*16)
        cp_async16(sm + OFF_W + i, (const char*)g_W16 + i);
    asm volatile("cp.async.commit_group;" ::: "memory");
    for (int idx = tid; idx < TT*16; idx += NTHR){
        int t = idx >> 4, p = idx & 15;
        float v0 = x[(size_t)(b0 + 2*p    )*TT + t];
        float v1 = x[(size_t)(b0 + 2*p + 1)*TT + t];
        x2_sh[t*16 + p] = __floats2half2_rn(v0, v1);
    }
    for (int i = tid; i < HBYTES/4; i += NTHR)
        ((float*)(sm + OFF_H))[i] = 0.0f;
    if (tid < 8) ((uint32_t*)(sm + OFF_F))[tid] = 1u;
    asm volatile("cp.async.wait_group 0;" ::: "memory");
    __syncthreads();

    // ---- per-thread constants (half2 dup for u0, u1) ----
    const int u0 = 16*w + (lane >> 2);
    const int u1 = u0 + 8;
    __half2 wi2[4][2], bs2[4][2];
    #pragma unroll
    for (int g = 0; g < 4; g++){
        wi2[g][0] = __float2half2_rn(Wih[g*HH + u0]);
        wi2[g][1] = __float2half2_rn(Wih[g*HH + u1]);
        bs2[g][0] = __float2half2_rn(bih[g*HH + u0] + bhh[g*HH + u0]);
        bs2[g][1] = __float2half2_rn(bih[g*HH + u1] + bhh[g*HH + u1]);
    }
    __half2 ch0[4], ch1[4];
    #pragma unroll
    for (int i = 0; i < 4; i++){
        ch0[i] = __float2half2_rn(0.0f);
        ch1[i] = __float2half2_rn(0.0f);
    }

    // ldmatrix address bases
    uint32_t Abase[4];
    #pragma unroll
    for (int mt = 0; mt < 4; mt++)
        Abase[mt] = smb + OFF_W +
            (uint32_t)(((mt*128 + 16*w + (lane & 15))*WSTRIDE + (lane >> 4)*8) * 2);
    const uint32_t AbaseT = smb + OFF_W +
            (uint32_t)(((512 + 16*w + (lane & 15))*WSTRIDE + (lane >> 4)*8) * 2);
    const uint32_t Brow = (uint32_t)((lane & 7) + ((lane >> 3) & 1)*8);
    const uint32_t Bb0  = smb + OFF_H + Brow*(HSTRIDE*2) + (uint32_t)((lane >> 4)*8)*2;
    const uint32_t Bb1  = Bb0 + 32;     // n0 = 16
    const int bq = 2*(lane & 3);        // batch pair within n8 tile

    // ---- cache A fragments for first 4 chunks of this warp's rotation ----
    uint32_t Areg[4][4][4];
    #pragma unroll
    for (int i = 0; i < 4; i++){
        const int kc = (w + i) & 7;
        #pragma unroll
        for (int mt = 0; mt < 4; mt++)
            ldsm4(Areg[i][mt], Abase[mt] + kc*32);
    }

    uint32_t bsel = 0;                  // byte offset of current read h buffer
    for (int t = 0; t < TT; t++){
        // init f16 accumulators: bias + x_t * w_in  (acch[mt][nt][0]=u0 pair, [1]=u1)
        uint32_t acch[4][4][2];
        __half2 x2[4];
        #pragma unroll
        for (int nt = 0; nt < 4; nt++)
            x2[nt] = x2_sh[t*16 + 4*nt + (lane & 3)];
        #pragma unroll
        for (int mt = 0; mt < 4; mt++)
            #pragma unroll
            for (int nt = 0; nt < 4; nt++){
                __half2 a0 = __hfma2(x2[nt], wi2[mt][0], bs2[mt][0]);
                __half2 a1 = __hfma2(x2[nt], wi2[mt][1], bs2[mt][1]);
                acch[mt][nt][0] = *(uint32_t*)&a0;
                acch[mt][nt][1] = *(uint32_t*)&a1;
            }

        const uint32_t Bc0 = Bb0 + bsel, Bc1 = Bb1 + bsel;
        const uint32_t want = (uint32_t)(t + 1);

        // chunk i=0 (kc = w): own chunk, flag set by this warp — no wait
        {
            const int kc = w;
            uint32_t bfr0[4], bfr1[4];
            ldsm4t(bfr0, Bc0 + kc*CHB);
            ldsm4t(bfr1, Bc1 + kc*CHB);
            #pragma unroll
            for (int mt = 0; mt < 4; mt++){
                mma16816h(acch[mt][0][0], acch[mt][0][1], Areg[0][mt], bfr0[0], bfr0[1]);
                mma16816h(acch[mt][1][0], acch[mt][1][1], Areg[0][mt], bfr0[2], bfr0[3]);
                mma16816h(acch[mt][2][0], acch[mt][2][1], Areg[0][mt], bfr1[0], bfr1[1]);
                mma16816h(acch[mt][3][0], acch[mt][3][1], Areg[0][mt], bfr1[2], bfr1[3]);
            }
        }
        // single warp-parallel wait for all producers of this step's h
        wait_all_flags(flagb, want, lane);

        // chunks i=1..3: cached A
        #pragma unroll
        for (int i = 1; i < 4; i++){
            const int kc = (w + i) & 7;
            uint32_t bfr0[4], bfr1[4];
            ldsm4t(bfr0, Bc0 + kc*CHB);
            ldsm4t(bfr1, Bc1 + kc*CHB);
            #pragma unroll
            for (int mt = 0; mt < 4; mt++){
                mma16816h(acch[mt][0][0], acch[mt][0][1], Areg[i][mt], bfr0[0], bfr0[1]);
                mma16816h(acch[mt][1][0], acch[mt][1][1], Areg[i][mt], bfr0[2], bfr0[3]);
                mma16816h(acch[mt][2][0], acch[mt][2][1], Areg[i][mt], bfr1[0], bfr1[1]);
                mma16816h(acch[mt][3][0], acch[mt][3][1], Areg[i][mt], bfr1[2], bfr1[3]);
            }
        }
        // chunks i=4..7: stream A from smem
        #pragma unroll
        for (int i = 4; i < 8; i++){
            const int kc = (w + i) & 7;
            uint32_t bfr0[4], bfr1[4];
            ldsm4t(bfr0, Bc0 + kc*CHB);
            ldsm4t(bfr1, Bc1 + kc*CHB);
            #pragma unroll
            for (int mt = 0; mt < 4; mt++){
                uint32_t a[4];
                ldsm4(a, Abase[mt] + kc*32);
                mma16816h(acch[mt][0][0], acch[mt][0][1], a, bfr0[0], bfr0[1]);
                mma16816h(acch[mt][1][0], acch[mt][1][1], a, bfr0[2], bfr0[3]);
                mma16816h(acch[mt][2][0], acch[mt][2][1], a, bfr1[0], bfr1[1]);
                mma16816h(acch[mt][3][0], acch[mt][3][1], a, bfr1[2], bfr1[3]);
            }
        }

        // f16x2 LSTM elementwise update (gates already packed half2 pairs)
        const uint32_t wsel = bsel ^ HBYTES;
        #pragma unroll
        for (int nt = 0; nt < 4; nt++){
            const int boff = (8*nt + bq)*2;
            {   // unit u0, batch pair
                __half2 iv = ht2_sig (*(__half2*)&acch[0][nt][0], h05);
                __half2 fv = ht2_sig (*(__half2*)&acch[1][nt][0], h05);
                __half2 gv = ht2_tanh(*(__half2*)&acch[2][nt][0]);
                __half2 ov = ht2_sig (*(__half2*)&acch[3][nt][0], h05);
                __half2 cv = __hfma2(fv, ch0[nt], __hmul2(iv, gv));
                ch0[nt] = cv;
                __half2 hv = __hmul2(ov, ht2_tanh(cv));
                *(__half2*)(sm + OFF_H + wsel + u0*(HSTRIDE*2) + boff) = hv;
            }
            {   // unit u1, batch pair
                __half2 iv = ht2_sig (*(__half2*)&acch[0][nt][1], h05);
                __half2 fv = ht2_sig (*(__half2*)&acch[1][nt][1], h05);
                __half2 gv = ht2_tanh(*(__half2*)&acch[2][nt][1]);
                __half2 ov = ht2_sig (*(__half2*)&acch[3][nt][1], h05);
                __half2 cv = __hfma2(fv, ch1[nt], __hmul2(iv, gv));
                ch1[nt] = cv;
                __half2 hv = __hmul2(ov, ht2_tanh(cv));
                *(__half2*)(sm + OFF_H + wsel + u1*(HSTRIDE*2) + boff) = hv;
            }
        }
        __syncwarp();
        if (lane == 0) st_rel(flagb + w*4, (uint32_t)(t + 2));
        bsel = wsel;
    }
    // final h is in buffer bsel

    // ---- MLP head: r1 = relu(W1 @ h + b1) via f32-acc MMA ----
    float racc[4][4];
    {
        float bv0 = b1[u0], bv1 = b1[u1];
        #pragma unroll
        for (int nt = 0; nt < 4; nt++){
            racc[nt][0] = bv0; racc[nt][1] = bv0;
            racc[nt][2] = bv1; racc[nt][3] = bv1;
        }
    }
    {
        wait_all_flags(flagb, (uint32_t)(TT + 1), lane);
        const uint32_t Bc0 = Bb0 + bsel, Bc1 = Bb1 + bsel;
        #pragma unroll
        for (int kc = 0; kc < 8; kc++){
            uint32_t bfr0[4], bfr1[4];
            ldsm4t(bfr0, Bc0 + kc*CHB);
            ldsm4t(bfr1, Bc1 + kc*CHB);
            uint32_t a[4];
            ldsm4(a, AbaseT + kc*32);
            mma16816(racc[0], a, bfr0[0], bfr0[1]);
            mma16816(racc[1], a, bfr0[2], bfr0[3]);
            mma16816(racc[2], a, bfr1[0], bfr1[1]);
            mma16816(racc[3], a, bfr1[2], bfr1[3]);
        }
    }
    __syncthreads();            // everyone past step loop; reuse x region as r1_sh
    float* r1_sh = (float*)(sm + OFF_X);   // [b][n] f32
    #pragma unroll
    for (int nt = 0; nt < 4; nt++)
        #pragma unroll
        for (int j = 0; j < 2; j++){
            int b = 8*nt + bq + j;
            r1_sh[b*HH + u0] = fmaxf(racc[nt][j],     0.0f);
            r1_sh[b*HH + u1] = fmaxf(racc[nt][2 + j], 0.0f);
        }
    __syncthreads();
    // stage W2 (5x128 f32) into h region (done with h)
    float* w2sh = (float*)(sm + OFF_H);
    for (int idx = tid; idx < 5*HH; idx += NTHR) w2sh[idx] = W2[idx];
    __syncthreads();

    // ---- r2 = r1 @ W2^T + b2; log_softmax (one thread per batch) ----
    if (tid < BT){
        const int b = tid;
        float r2[5];
        #pragma unroll
        for (int o = 0; o < 5; o++) r2[o] = b2[o];
        for (int kk = 0; kk < HH; kk++){
            int k = (kk + b*4) & (HH - 1);
            float v = r1_sh[b*HH + k];
            #pragma unroll
            for (int o = 0; o < 5; o++) r2[o] = fmaf(v, w2sh[o*HH + k], r2[o]);
        }
        float m = r2[0];
        #pragma unroll
        for (int o = 1; o < 5; o++) m = fmaxf(m, r2[o]);
        float s = 0.0f;
        #pragma unroll
        for (int o = 0; o < 5; o++) s += __expf(r2[o] - m);
        float l = m + __logf(s);
        #pragma unroll
        for (int o = 0; o < 5; o++)
            out[(size_t)(b0 + b)*5 + o] = r2[o] - l;
    }
}

extern "C" void kernel_launch(void* const* d_in, const int* in_sizes, int n_in,
                              void* d_out, int out_size){
    const float* x   = (const float*)d_in[0];
    const float* Wih = (const float*)d_in[1];
    const float* Whh = (const float*)d_in[2];
    const float* bih = (const float*)d_in[3];
    const float* bhh = (const float*)d_in[4];
    const float* W1  = (const float*)d_in[5];
    const float* b1  = (const float*)d_in[6];
    const float* W2  = (const float*)d_in[7];
    const float* b2  = (const float*)d_in[8];
    float* out = (float*)d_out;

    prep_kernel<<<128, 256>>>(Whh, W1);

    cudaFuncSetAttribute(lstm_kernel,
                         cudaFuncAttributeMaxDynamicSharedMemorySize, SMEM_BYTES);
    lstm_kernel<<<NCTA, NTHR, SMEM_BYTES>>>(x, Wih, bih, bhh, b1, W2, b2, out);
}

// round 13
// speedup vs baseline: 1.2848x; 1.0160x over previous
#include <cuda_runtime.h>
#include <cuda_fp16.h>
#include <cstdint>

#define TT 140
#define HH 128
#define BT 32
#define NCTA 128
#define NTHR 256

#define WSTRIDE 136                    // halfs per weight row (272 B, conflict-free LDSM)
#define WROWS   640                    // 512 gate rows + 128 W1 rows
#define WBYTES  (WROWS*WSTRIDE*2)      // 174080
#define HSTRIDE 40                     // halfs per h row (80 B, conflict-free)
#define HBYTES  (HH*HSTRIDE*2)         // 10240
#define CHB     (16*HSTRIDE*2)         // bytes per 16-row h chunk
#define OFF_W   0
#define OFF_H   WBYTES                 // two h buffers
#define OFF_X   (OFF_H + 2*HBYTES)     // x2_sh [t][16] half2; tail reuses as r1_sh f32
#define SMEM_BYTES (OFF_X + TT*BT*4 + 64)
#define OFF_F   (OFF_X + TT*BT*4)      // 8 chunk flags

// f16 weights, padded layout: rows 0..511 = W_hh (gate-major), rows 512..639 = W1
__device__ __align__(16) unsigned short g_W16[WROWS*WSTRIDE];

// ---------------- helpers ----------------
__device__ __forceinline__ uint32_t smem_u32(const void* p){
    uint32_t a;
    asm("{ .reg .u64 t; cvta.to.shared.u64 t, %1; cvt.u32.u64 %0, t; }"
        : "=r"(a) : "l"(p));
    return a;
}
__device__ __forceinline__ void cp_async16(void* s, const void* g){
    unsigned a = smem_u32(s);
    asm volatile("cp.async.cg.shared.global [%0],[%1],16;" :: "r"(a), "l"(g));
}
__device__ __forceinline__ void ldsm4(uint32_t* r, uint32_t addr){
    asm volatile("ldmatrix.sync.aligned.m8n8.x4.shared.b16 {%0,%1,%2,%3},[%4];"
        : "=r"(r[0]),"=r"(r[1]),"=r"(r[2]),"=r"(r[3]) : "r"(addr));
}
__device__ __forceinline__ void ldsm4t(uint32_t* r, uint32_t addr){
    asm volatile("ldmatrix.sync.aligned.m8n8.x4.trans.shared.b16 {%0,%1,%2,%3},[%4];"
        : "=r"(r[0]),"=r"(r[1]),"=r"(r[2]),"=r"(r[3]) : "r"(addr));
}
// f16-accumulator MMA: D,C packed half2 (d0 = rows r, d1 = rows r+8)
__device__ __forceinline__ void mma16816h(uint32_t& d0, uint32_t& d1,
                                          const uint32_t* a,
                                          uint32_t b0, uint32_t b1){
    asm volatile("mma.sync.aligned.m16n8k16.row.col.f16.f16.f16.f16 "
        "{%0,%1},{%2,%3,%4,%5},{%6,%7},{%0,%1};"
        : "+r"(d0),"+r"(d1)
        : "r"(a[0]),"r"(a[1]),"r"(a[2]),"r"(a[3]),"r"(b0),"r"(b1));
}
// f32-accumulator MMA (used once in the MLP head)
__device__ __forceinline__ void mma16816(float* d, const uint32_t* a,
                                         uint32_t b0, uint32_t b1){
    asm volatile("mma.sync.aligned.m16n8k16.row.col.f32.f16.f16.f32 "
        "{%0,%1,%2,%3},{%4,%5,%6,%7},{%8,%9},{%0,%1,%2,%3};"
        : "+f"(d[0]),"+f"(d[1]),"+f"(d[2]),"+f"(d[3])
        : "r"(a[0]),"r"(a[1]),"r"(a[2]),"r"(a[3]),"r"(b0),"r"(b1));
}
__device__ __forceinline__ __half2 ht2_tanh(__half2 x){
    uint32_t xu = *(uint32_t*)&x, r;
    asm("tanh.approx.f16x2 %0,%1;" : "=r"(r) : "r"(xu));
    return *(__half2*)&r;
}
__device__ __forceinline__ __half2 ht2_sig(__half2 x, __half2 h05){
    return __hfma2(ht2_tanh(__hmul2(x, h05)), h05, h05);
}
__device__ __forceinline__ uint32_t ld_acq(uint32_t a){
    uint32_t v;
    asm volatile("ld.acquire.cta.shared.u32 %0,[%1];" : "=r"(v) : "r"(a) : "memory");
    return v;
}
__device__ __forceinline__ void st_rel(uint32_t a, uint32_t v){
    asm volatile("st.release.cta.shared.u32 [%0],%1;" :: "r"(a), "r"(v) : "memory");
}
__device__ __forceinline__ void wait_all_flags(uint32_t flagb, uint32_t want, int lane){
    uint32_t v = (lane < 8) ? ld_acq(flagb + lane*4) : want;
    while (!__all_sync(0xffffffffu, v >= want)){
        asm volatile("nanosleep.u32 20;");
        v = (lane < 8) ? ld_acq(flagb + lane*4) : want;
    }
    __syncwarp();
}

// ---------------- prep: convert weights to f16 padded layout ----------------
__global__ void prep_kernel(const float* __restrict__ Whh,
                            const float* __restrict__ W1){
    int i = blockIdx.x * blockDim.x + threadIdx.x;
    int stride = gridDim.x * blockDim.x;
    for (int idx = i; idx < WROWS*HH; idx += stride){
        int row = idx >> 7, k = idx & 127;
        float v = (row < 512) ? Whh[row*HH + k] : W1[(row - 512)*HH + k];
        __half hv = __float2half_rn(v);
        g_W16[row*WSTRIDE + k] = *(unsigned short*)&hv;
    }
}

// ---------------- main persistent LSTM kernel ----------------
__global__ __launch_bounds__(NTHR, 1)
void lstm_kernel(const float* __restrict__ x,
                 const float* __restrict__ Wih,
                 const float* __restrict__ bih,
                 const float* __restrict__ bhh,
                 const float* __restrict__ b1,
                 const float* __restrict__ W2,
                 const float* __restrict__ b2,
                 float* __restrict__ out){
    extern __shared__ char sm[];
    const uint32_t smb = smem_u32(sm);
    const int tid  = threadIdx.x;
    const int lane = tid & 31;
    const int w    = tid >> 5;          // warp 0..7, owns units 16w..16w+15
    const int b0   = blockIdx.x * BT;
    __half2* x2_sh = (__half2*)(sm + OFF_X);   // [t][16] batch pairs
    const uint32_t flagb = smb + OFF_F;
    const __half2 h05 = __float2half2_rn(0.5f);

    // ---- stage W (f16) via cp.async; x (as half2 pairs); zero h buffer 0 ----
    for (int i = tid*16; i < WBYTES; i += NTHR*16)
        cp_async16(sm + OFF_W + i, (const char*)g_W16 + i);
    asm volatile("cp.async.commit_group;" ::: "memory");
    for (int idx = tid; idx < TT*16; idx += NTHR){
        int t = idx >> 4, p = idx & 15;
        float v0 = x[(size_t)(b0 + 2*p    )*TT + t];
        float v1 = x[(size_t)(b0 + 2*p + 1)*TT + t];
        x2_sh[t*16 + p] = __floats2half2_rn(v0, v1);
    }
    for (int i = tid; i < HBYTES/4; i += NTHR)
        ((float*)(sm + OFF_H))[i] = 0.0f;
    if (tid < 8) ((uint32_t*)(sm + OFF_F))[tid] = 1u;
    asm volatile("cp.async.wait_group 0;" ::: "memory");
    __syncthreads();

    // ---- per-thread constants (half2 dup for u0, u1) ----
    const int u0 = 16*w + (lane >> 2);
    const int u1 = u0 + 8;
    __half2 wi2[4][2], bs2[4][2];
    #pragma unroll
    for (int g = 0; g < 4; g++){
        wi2[g][0] = __float2half2_rn(Wih[g*HH + u0]);
        wi2[g][1] = __float2half2_rn(Wih[g*HH + u1]);
        bs2[g][0] = __float2half2_rn(bih[g*HH + u0] + bhh[g*HH + u0]);
        bs2[g][1] = __float2half2_rn(bih[g*HH + u1] + bhh[g*HH + u1]);
    }
    __half2 ch0[4], ch1[4];
    #pragma unroll
    for (int i = 0; i < 4; i++){
        ch0[i] = __float2half2_rn(0.0f);
        ch1[i] = __float2half2_rn(0.0f);
    }

    // ldmatrix address bases
    uint32_t Abase[4];
    #pragma unroll
    for (int mt = 0; mt < 4; mt++)
        Abase[mt] = smb + OFF_W +
            (uint32_t)(((mt*128 + 16*w + (lane & 15))*WSTRIDE + (lane >> 4)*8) * 2);
    const uint32_t AbaseT = smb + OFF_W +
            (uint32_t)(((512 + 16*w + (lane & 15))*WSTRIDE + (lane >> 4)*8) * 2);
    const uint32_t Brow = (uint32_t)((lane & 7) + ((lane >> 3) & 1)*8);
    const uint32_t Bb0  = smb + OFF_H + Brow*(HSTRIDE*2) + (uint32_t)((lane >> 4)*8)*2;
    const uint32_t Bb1  = Bb0 + 32;     // n0 = 16
    const int bq = 2*(lane & 3);        // batch pair within n8 tile

    uint32_t bsel = 0;                  // byte offset of current read h buffer
    for (int t = 0; t < TT; t++){
        const uint32_t Bc0 = Bb0 + bsel, Bc1 = Bb1 + bsel;
        const uint32_t want = (uint32_t)(t + 1);

        // double-buffered fragments (prefetch distance 1)
        uint32_t Ab[2][4][4], Bb[2][8];

        // load chunk 0 (kc = w): own chunk, no wait needed
        ldsm4t(&Bb[0][0], Bc0 + w*CHB);
        ldsm4t(&Bb[0][4], Bc1 + w*CHB);
        #pragma unroll
        for (int mt = 0; mt < 4; mt++)
            ldsm4(Ab[0][mt], Abase[mt] + w*32);

        // init f16 accumulators: bias + x_t * w_in (fills LDS latency)
        uint32_t acch[4][4][2];
        __half2 x2[4];
        #pragma unroll
        for (int nt = 0; nt < 4; nt++)
            x2[nt] = x2_sh[t*16 + 4*nt + (lane & 3)];
        #pragma unroll
        for (int mt = 0; mt < 4; mt++)
            #pragma unroll
            for (int nt = 0; nt < 4; nt++){
                __half2 a0 = __hfma2(x2[nt], wi2[mt][0], bs2[mt][0]);
                __half2 a1 = __hfma2(x2[nt], wi2[mt][1], bs2[mt][1]);
                acch[mt][nt][0] = *(uint32_t*)&a0;
                acch[mt][nt][1] = *(uint32_t*)&a1;
            }

        // MMA chunk 0
        #pragma unroll
        for (int mt = 0; mt < 4; mt++){
            mma16816h(acch[mt][0][0], acch[mt][0][1], Ab[0][mt], Bb[0][0], Bb[0][1]);
            mma16816h(acch[mt][1][0], acch[mt][1][1], Ab[0][mt], Bb[0][2], Bb[0][3]);
            mma16816h(acch[mt][2][0], acch[mt][2][1], Ab[0][mt], Bb[0][4], Bb[0][5]);
            mma16816h(acch[mt][3][0], acch[mt][3][1], Ab[0][mt], Bb[0][6], Bb[0][7]);
        }

        // wait for all producers of this step's h, then pipeline chunks 1..7
        wait_all_flags(flagb, want, lane);
        {
            const int kc1 = (w + 1) & 7;
            ldsm4t(&Bb[1][0], Bc0 + kc1*CHB);
            ldsm4t(&Bb[1][4], Bc1 + kc1*CHB);
            #pragma unroll
            for (int mt = 0; mt < 4; mt++)
                ldsm4(Ab[1][mt], Abase[mt] + kc1*32);
        }
        #pragma unroll
        for (int i = 1; i < 8; i++){
            const int cb = i & 1;
            if (i < 7){
                const int kcn = (w + i + 1) & 7;
                const int nb = cb ^ 1;
                ldsm4t(&Bb[nb][0], Bc0 + kcn*CHB);
                ldsm4t(&Bb[nb][4], Bc1 + kcn*CHB);
                #pragma unroll
                for (int mt = 0; mt < 4; mt++)
                    ldsm4(Ab[nb][mt], Abase[mt] + kcn*32);
            }
            #pragma unroll
            for (int mt = 0; mt < 4; mt++){
                mma16816h(acch[mt][0][0], acch[mt][0][1], Ab[cb][mt], Bb[cb][0], Bb[cb][1]);
                mma16816h(acch[mt][1][0], acch[mt][1][1], Ab[cb][mt], Bb[cb][2], Bb[cb][3]);
                mma16816h(acch[mt][2][0], acch[mt][2][1], Ab[cb][mt], Bb[cb][4], Bb[cb][5]);
                mma16816h(acch[mt][3][0], acch[mt][3][1], Ab[cb][mt], Bb[cb][6], Bb[cb][7]);
            }
        }

        // f16x2 LSTM elementwise update (gates already packed half2 pairs)
        const uint32_t wsel = bsel ^ HBYTES;
        #pragma unroll
        for (int nt = 0; nt < 4; nt++){
            const int boff = (8*nt + bq)*2;
            {   // unit u0, batch pair
                __half2 iv = ht2_sig (*(__half2*)&acch[0][nt][0], h05);
                __half2 fv = ht2_sig (*(__half2*)&acch[1][nt][0], h05);
                __half2 gv = ht2_tanh(*(__half2*)&acch[2][nt][0]);
                __half2 ov = ht2_sig (*(__half2*)&acch[3][nt][0], h05);
                __half2 cv = __hfma2(fv, ch0[nt], __hmul2(iv, gv));
                ch0[nt] = cv;
                __half2 hv = __hmul2(ov, ht2_tanh(cv));
                *(__half2*)(sm + OFF_H + wsel + u0*(HSTRIDE*2) + boff) = hv;
            }
            {   // unit u1, batch pair
                __half2 iv = ht2_sig (*(__half2*)&acch[0][nt][1], h05);
                __half2 fv = ht2_sig (*(__half2*)&acch[1][nt][1], h05);
                __half2 gv = ht2_tanh(*(__half2*)&acch[2][nt][1]);
                __half2 ov = ht2_sig (*(__half2*)&acch[3][nt][1], h05);
                __half2 cv = __hfma2(fv, ch1[nt], __hmul2(iv, gv));
                ch1[nt] = cv;
                __half2 hv = __hmul2(ov, ht2_tanh(cv));
                *(__half2*)(sm + OFF_H + wsel + u1*(HSTRIDE*2) + boff) = hv;
            }
        }
        __syncwarp();
        if (lane == 0) st_rel(flagb + w*4, (uint32_t)(t + 2));
        bsel = wsel;
    }
    // final h is in buffer bsel

    // ---- MLP head: r1 = relu(W1 @ h + b1) via f32-acc MMA ----
    float racc[4][4];
    {
        float bv0 = b1[u0], bv1 = b1[u1];
        #pragma unroll
        for (int nt = 0; nt < 4; nt++){
            racc[nt][0] = bv0; racc[nt][1] = bv0;
            racc[nt][2] = bv1; racc[nt][3] = bv1;
        }
    }
    {
        wait_all_flags(flagb, (uint32_t)(TT + 1), lane);
        const uint32_t Bc0 = Bb0 + bsel, Bc1 = Bb1 + bsel;
        #pragma unroll
        for (int kc = 0; kc < 8; kc++){
            uint32_t bfr0[4], bfr1[4];
            ldsm4t(bfr0, Bc0 + kc*CHB);
            ldsm4t(bfr1, Bc1 + kc*CHB);
            uint32_t a[4];
            ldsm4(a, AbaseT + kc*32);
            mma16816(racc[0], a, bfr0[0], bfr0[1]);
            mma16816(racc[1], a, bfr0[2], bfr0[3]);
            mma16816(racc[2], a, bfr1[0], bfr1[1]);
            mma16816(racc[3], a, bfr1[2], bfr1[3]);
        }
    }
    __syncthreads();            // everyone past step loop; reuse x region as r1_sh
    float* r1_sh = (float*)(sm + OFF_X);   // [b][n] f32
    #pragma unroll
    for (int nt = 0; nt < 4; nt++)
        #pragma unroll
        for (int j = 0; j < 2; j++){
            int b = 8*nt + bq + j;
            r1_sh[b*HH + u0] = fmaxf(racc[nt][j],     0.0f);
            r1_sh[b*HH + u1] = fmaxf(racc[nt][2 + j], 0.0f);
        }
    __syncthreads();
    // stage W2 (5x128 f32) into h region (done with h)
    float* w2sh = (float*)(sm + OFF_H);
    for (int idx = tid; idx < 5*HH; idx += NTHR) w2sh[idx] = W2[idx];
    __syncthreads();

    // ---- r2 = r1 @ W2^T + b2; log_softmax (one thread per batch) ----
    if (tid < BT){
        const int b = tid;
        float r2[5];
        #pragma unroll
        for (int o = 0; o < 5; o++) r2[o] = b2[o];
        for (int kk = 0; kk < HH; kk++){
            int k = (kk + b*4) & (HH - 1);
            float v = r1_sh[b*HH + k];
            #pragma unroll
            for (int o = 0; o < 5; o++) r2[o] = fmaf(v, w2sh[o*HH + k], r2[o]);
        }
        float m = r2[0];
        #pragma unroll
        for (int o = 1; o < 5; o++) m = fmaxf(m, r2[o]);
        float s = 0.0f;
        #pragma unroll
        for (int o = 0; o < 5; o++) s += __expf(r2[o] - m);
        float l = m + __logf(s);
        #pragma unroll
        for (int o = 0; o < 5; o++)
            out[(size_t)(b0 + b)*5 + o] = r2[o] - l;
    }
}

extern "C" void kernel_launch(void* const* d_in, const int* in_sizes, int n_in,
                              void* d_out, int out_size){
    const float* x   = (const float*)d_in[0];
    const float* Wih = (const float*)d_in[1];
    const float* Whh = (const float*)d_in[2];
    const float* bih = (const float*)d_in[3];
    const float* bhh = (const float*)d_in[4];
    const float* W1  = (const float*)d_in[5];
    const float* b1  = (const float*)d_in[6];
    const float* W2  = (const float*)d_in[7];
    const float* b2  = (const float*)d_in[8];
    float* out = (float*)d_out;

    prep_kernel<<<128, 256>>>(Whh, W1);

    cudaFuncSetAttribute(lstm_kernel,
                         cudaFuncAttributeMaxDynamicSharedMemorySize, SMEM_BYTES);
    lstm_kernel<<<NCTA, NTHR, SMEM_BYTES>>>(x, Wih, bih, bhh, b1, W2, b2, out);
}